// round 1
// baseline (speedup 1.0000x reference)
#include <cuda_runtime.h>
#include <math.h>

// Problem constants (fixed by the dataset)
#define NN 50000
#define EE 500000
#define ET (EE + NN)

// ---------------- scratch (device globals; no runtime allocation) ----------------
__device__ __align__(16) float g_h1[NN * 256];
__device__ __align__(16) float g_x1[NN * 256];
__device__ __align__(16) float g_h2[NN * 128];
__device__ __align__(16) float g_x2[NN * 128];
__device__ __align__(16) float g_ealpha[ET * 2];
__device__ float g_asrc1[NN * 2], g_adst1[NN * 2], g_m1[NN * 2], g_s1[NN * 2];
__device__ float g_asrc2[NN], g_adst2[NN], g_m2[NN], g_s2[NN];
__device__ __align__(16) float g_yl[NN * 96];
__device__ __align__(16) float g_ya[NN * 96];
__device__ __align__(16) float g_yb[NN * 2];
__device__ float g_statL[192], g_statA[192], g_statB[4];
__device__ float g_scaleL[96], g_shiftL[96];
__device__ float g_scaleA[96], g_shiftA[96];
__device__ float g_scaleB[2], g_shiftB[2];
__device__ int g_is64;

// ---------------- helpers ----------------
__device__ __forceinline__ void atomicMaxF(float* addr, float v) {
    if (v >= 0.f) atomicMax((int*)addr, __float_as_int(v));
    else          atomicMin((unsigned int*)addr, __float_as_uint(v));
}

__device__ __forceinline__ void redAddV4(float* a, float x, float y, float z, float w) {
    asm volatile("red.global.add.v4.f32 [%0], {%1, %2, %3, %4};"
                 :: "l"(a), "f"(x), "f"(y), "f"(z), "f"(w) : "memory");
}

// Edge loader: handles int64 or int32 edge_index, and appended self-loops.
__device__ __forceinline__ void load_edge(const void* ei, int e, int E, int& s, int& d) {
    if (e >= E) { s = d = e - E; return; }
    if (g_is64) {
        const long long* p = (const long long*)ei;
        s = (int)p[e];
        d = (int)p[E + e];
    } else {
        const int* p = (const int*)ei;
        s = p[e];
        d = p[E + e];
    }
}

// Detect int64 vs int32 edge_index: int64 values < 2^31 have zero high words.
__global__ void detect_kernel(const int* ei32) {
    __shared__ int found;
    if (threadIdx.x == 0) found = 0;
    __syncthreads();
    for (int i = threadIdx.x; i < 4096; i += blockDim.x)
        if (ei32[2 * i + 1] != 0) found = 1;
    __syncthreads();
    if (threadIdx.x == 0) g_is64 = (found == 0) ? 1 : 0;
}

// Zero/initialize all accumulators for this call.
__global__ void init_kernel(int n) {
    int i = blockIdx.x * blockDim.x + threadIdx.x;
    const float NEG_INF = __int_as_float(0xff800000);
    if (i < n * 256) g_x1[i] = 0.f;
    if (i < n * 128) g_x2[i] = 0.f;
    if (i < n * 2) { g_m1[i] = NEG_INF; g_s1[i] = 0.f; }
    if (i < n)     { g_m2[i] = NEG_INF; g_s2[i] = 0.f; }
    if (i < 192)   { g_statL[i] = 0.f; g_statA[i] = 0.f; }
    if (i < 4)     g_statB[i] = 0.f;
}

// ---------------- generic fp32 tiled GEMM ----------------
// C[M,N] = op(A) @ B (+bias)(+relu). A is split: columns [0,K1) from A1 (ld=K1),
// [K1,K) from A2 (ld=K2). Optional per-K affine transform on A (BN folding).
#define BM 64
#define BN 64
#define BK 16
template<bool RELU>
__global__ void gemm_kernel(const float* __restrict__ A1, int K1,
                            const float* __restrict__ A2, int K2,
                            const float* __restrict__ B,
                            const float* __restrict__ bias,
                            const float* __restrict__ a_scale,
                            const float* __restrict__ a_shift,
                            float* __restrict__ C,
                            int M, int N, int K)
{
    __shared__ float As[BK][BM + 1];
    __shared__ float Bs[BK][BN + 4];
    int tid = threadIdx.x;          // 256 threads
    int bm0 = blockIdx.y * BM;
    int bn0 = blockIdx.x * BN;
    int tx = tid & 15, ty = tid >> 4;
    float acc[4][4] = {};

    for (int k0 = 0; k0 < K; k0 += BK) {
        #pragma unroll
        for (int i = 0; i < 4; i++) {
            int idx = tid + i * 256;
            int r = idx >> 4, c = idx & 15;
            int row = bm0 + r, kk = k0 + c;
            float v = 0.f;
            if (row < M) {
                v = (kk < K1) ? A1[(size_t)row * K1 + kk]
                              : A2[(size_t)row * K2 + (kk - K1)];
                if (a_scale) v = v * a_scale[kk] + a_shift[kk];
            }
            As[c][r] = v;
        }
        #pragma unroll
        for (int i = 0; i < 4; i++) {
            int idx = tid + i * 256;
            int r = idx >> 6, c = idx & 63;
            int col = bn0 + c;
            Bs[r][c] = (col < N) ? B[(size_t)(k0 + r) * N + col] : 0.f;
        }
        __syncthreads();
        #pragma unroll
        for (int kk = 0; kk < BK; kk++) {
            float a[4], b[4];
            #pragma unroll
            for (int i = 0; i < 4; i++) a[i] = As[kk][ty * 4 + i];
            #pragma unroll
            for (int j = 0; j < 4; j++) b[j] = Bs[kk][tx * 4 + j];
            #pragma unroll
            for (int i = 0; i < 4; i++)
                #pragma unroll
                for (int j = 0; j < 4; j++)
                    acc[i][j] = fmaf(a[i], b[j], acc[i][j]);
        }
        __syncthreads();
    }

    #pragma unroll
    for (int i = 0; i < 4; i++) {
        int row = bm0 + ty * 4 + i;
        if (row >= M) continue;
        #pragma unroll
        for (int j = 0; j < 4; j++) {
            int col = bn0 + tx * 4 + j;
            if (col >= N) continue;
            float v = acc[i][j];
            if (bias) v += bias[col];
            if (RELU) v = fmaxf(v, 0.f);
            C[(size_t)row * N + col] = v;
        }
    }
}

// ---------------- attention source/dest logits: warp per node ----------------
template<int HEADS>
__global__ void att_dots_kernel(const float* __restrict__ h,
                                const float* __restrict__ att_src,
                                const float* __restrict__ att_dst,
                                float* __restrict__ asrc, float* __restrict__ adst, int n)
{
    int warp = (blockIdx.x * blockDim.x + threadIdx.x) >> 5;
    int lane = threadIdx.x & 31;
    if (warp >= n) return;
    const float* row = h + (size_t)warp * (HEADS * 128);
    #pragma unroll
    for (int hd = 0; hd < HEADS; hd++) {
        float ss = 0.f, sd = 0.f;
        #pragma unroll
        for (int c = lane; c < 128; c += 32) {
            float v = row[hd * 128 + c];
            ss = fmaf(v, att_src[hd * 128 + c], ss);
            sd = fmaf(v, att_dst[hd * 128 + c], sd);
        }
        #pragma unroll
        for (int o = 16; o; o >>= 1) {
            ss += __shfl_xor_sync(0xffffffffu, ss, o);
            sd += __shfl_xor_sync(0xffffffffu, sd, o);
        }
        if (lane == 0) {
            asrc[warp * HEADS + hd] = ss;
            adst[warp * HEADS + hd] = sd;
        }
    }
}

// ---------------- edge passes ----------------
template<int HEADS>
__global__ void edge_max_kernel(const void* ei, int E, int n,
                                const float* __restrict__ asrc,
                                const float* __restrict__ adst,
                                float* __restrict__ ealpha, float* __restrict__ m)
{
    int e = blockIdx.x * blockDim.x + threadIdx.x;
    if (e >= E + n) return;
    int s, d; load_edge(ei, e, E, s, d);
    #pragma unroll
    for (int hd = 0; hd < HEADS; hd++) {
        float a = asrc[s * HEADS + hd] + adst[d * HEADS + hd];
        a = (a > 0.f) ? a : 0.2f * a;     // leaky relu, slope 0.2
        ealpha[e * HEADS + hd] = a;
        atomicMaxF(&m[d * HEADS + hd], a);
    }
}

template<int HEADS>
__global__ void edge_exp_kernel(const void* ei, int E, int n,
                                float* __restrict__ ealpha,
                                const float* __restrict__ m, float* __restrict__ ssum)
{
    int e = blockIdx.x * blockDim.x + threadIdx.x;
    if (e >= E + n) return;
    int s, d; load_edge(ei, e, E, s, d);
    (void)s;
    #pragma unroll
    for (int hd = 0; hd < HEADS; hd++) {
        float ex = __expf(ealpha[e * HEADS + hd] - m[d * HEADS + hd]);
        ealpha[e * HEADS + hd] = ex;
        atomicAdd(&ssum[d * HEADS + hd], ex);
    }
}

// weighted scatter: warp per edge; vector red.global.add.v4.f32
template<int HEADS>
__global__ void scatter_kernel(const void* ei, int E, int n,
                               const float* __restrict__ h,
                               const float* __restrict__ ealpha,
                               const float* __restrict__ ssum,
                               float* __restrict__ out)
{
    int gw = (int)(((size_t)blockIdx.x * blockDim.x + threadIdx.x) >> 5);
    int lane = threadIdx.x & 31;
    if (gw >= E + n) return;
    int s, d; load_edge(ei, gw, E, s, d);
    const int CPL = HEADS * 128 / 32;     // 8 (conv1) or 4 (conv2)
    int c0 = lane * CPL;
    int hd = c0 >> 7;
    float w = ealpha[gw * HEADS + hd] / (ssum[d * HEADS + hd] + 1e-16f);
    const float* hp = h + (size_t)s * (HEADS * 128) + c0;
    float* op = out + (size_t)d * (HEADS * 128) + c0;
    #pragma unroll
    for (int v = 0; v < CPL / 4; v++) {
        float4 t = ((const float4*)hp)[v];
        redAddV4(op + v * 4, t.x * w, t.y * w, t.z * w, t.w * w);
    }
}

__global__ void bias_add_kernel(float* __restrict__ x, const float* __restrict__ bias,
                                int total, int mask)
{
    int i = blockIdx.x * blockDim.x + threadIdx.x;
    if (i < total) x[i] += bias[i & mask];
}

// ---------------- batchnorm stats ----------------
__global__ void stats_cols_kernel(const float* __restrict__ y, int M, int ncols,
                                  float* __restrict__ stats)
{
    int col = threadIdx.x;          // blockDim.x == ncols
    float s = 0.f, ss = 0.f;
    for (int r = blockIdx.x; r < M; r += gridDim.x) {
        float v = y[(size_t)r * ncols + col];
        s += v; ss = fmaf(v, v, ss);
    }
    atomicAdd(&stats[col], s);
    atomicAdd(&stats[ncols + col], ss);
}

__global__ void stats2_kernel(const float* __restrict__ y, int M, float* __restrict__ stats)
{
    int t = blockIdx.x * blockDim.x + threadIdx.x;
    int stride = gridDim.x * blockDim.x;
    float s0 = 0.f, ss0 = 0.f, s1 = 0.f, ss1 = 0.f;
    for (int r = t; r < M; r += stride) {
        float2 v = ((const float2*)y)[r];
        s0 += v.x; ss0 = fmaf(v.x, v.x, ss0);
        s1 += v.y; ss1 = fmaf(v.y, v.y, ss1);
    }
    #pragma unroll
    for (int o = 16; o; o >>= 1) {
        s0  += __shfl_xor_sync(0xffffffffu, s0, o);
        ss0 += __shfl_xor_sync(0xffffffffu, ss0, o);
        s1  += __shfl_xor_sync(0xffffffffu, s1, o);
        ss1 += __shfl_xor_sync(0xffffffffu, ss1, o);
    }
    if ((threadIdx.x & 31) == 0) {
        atomicAdd(&stats[0], s0);
        atomicAdd(&stats[1], s1);
        atomicAdd(&stats[2], ss0);
        atomicAdd(&stats[3], ss1);
    }
}

__global__ void bn_finalize_kernel(const float* __restrict__ stats,
                                   const float* __restrict__ gamma,
                                   const float* __restrict__ beta,
                                   float* __restrict__ scale, float* __restrict__ shift,
                                   int M, int ncols)
{
    int c = threadIdx.x;
    if (c >= ncols) return;
    float inv = 1.f / (float)M;
    float mu = stats[c] * inv;
    float var = stats[ncols + c] * inv - mu * mu;
    float sc = gamma[c] * rsqrtf(var + 1e-5f);
    scale[c] = sc;
    shift[c] = beta[c] - mu * sc;
}

__global__ void final_kernel(const float* __restrict__ yb,
                             const float* __restrict__ scale,
                             const float* __restrict__ shift,
                             float* __restrict__ out, int total)
{
    int i = blockIdx.x * blockDim.x + threadIdx.x;
    if (i < total) {
        int c = i & 1;
        out[i] = fmaf(scale[c], yb[i], shift[c]);
    }
}

// ---------------- launch ----------------
static inline void* sym(const void* s) {
    void* p = nullptr;
    cudaGetSymbolAddress(&p, s);
    return p;
}

extern "C" void kernel_launch(void* const* d_in, const int* in_sizes, int n_in,
                              void* d_out, int out_size)
{
    const float* x        = (const float*)d_in[0];
    const void*  ei       = d_in[1];
    const float* W1       = (const float*)d_in[2];
    const float* att_src1 = (const float*)d_in[3];
    const float* att_dst1 = (const float*)d_in[4];
    const float* bias1    = (const float*)d_in[5];
    const float* W2       = (const float*)d_in[6];
    const float* att_src2 = (const float*)d_in[7];
    const float* att_dst2 = (const float*)d_in[8];
    const float* bias2    = (const float*)d_in[9];
    const float* Wl = (const float*)d_in[10];
    const float* bl = (const float*)d_in[11];
    const float* gl = (const float*)d_in[12];
    const float* betal = (const float*)d_in[13];
    const float* Wa = (const float*)d_in[14];
    const float* ba = (const float*)d_in[15];
    const float* ga = (const float*)d_in[16];
    const float* betaa = (const float*)d_in[17];
    const float* Wb = (const float*)d_in[18];
    const float* bb = (const float*)d_in[19];
    const float* gb = (const float*)d_in[20];
    const float* betab = (const float*)d_in[21];
    float* out = (float*)d_out;

    int n = in_sizes[0] / 128;      // 50000
    int E = in_sizes[1] / 2;        // 500000
    int Etot = E + n;

    float* h1 = (float*)sym(g_h1);
    float* x1 = (float*)sym(g_x1);
    float* h2 = (float*)sym(g_h2);
    float* x2 = (float*)sym(g_x2);
    float* ealpha = (float*)sym(g_ealpha);
    float* asrc1 = (float*)sym(g_asrc1);
    float* adst1 = (float*)sym(g_adst1);
    float* m1 = (float*)sym(g_m1);
    float* s1 = (float*)sym(g_s1);
    float* asrc2 = (float*)sym(g_asrc2);
    float* adst2 = (float*)sym(g_adst2);
    float* m2 = (float*)sym(g_m2);
    float* s2 = (float*)sym(g_s2);
    float* yl = (float*)sym(g_yl);
    float* ya = (float*)sym(g_ya);
    float* yb = (float*)sym(g_yb);
    float* statL = (float*)sym(g_statL);
    float* statA = (float*)sym(g_statA);
    float* statB = (float*)sym(g_statB);
    float* scaleL = (float*)sym(g_scaleL);
    float* shiftL = (float*)sym(g_shiftL);
    float* scaleA = (float*)sym(g_scaleA);
    float* shiftA = (float*)sym(g_shiftA);
    float* scaleB = (float*)sym(g_scaleB);
    float* shiftB = (float*)sym(g_shiftB);

    // 0) edge dtype detect + init accumulators
    detect_kernel<<<1, 256>>>((const int*)ei);
    {
        int tot = n * 256;
        init_kernel<<<(tot + 255) / 256, 256>>>(n);
    }

    dim3 g256(256);
    int edge_blocks = (Etot + 255) / 256;
    int scat_blocks = (int)(((size_t)Etot * 32 + 255) / 256);
    int warp_blocks = (n + 7) / 8;

    // ---------- conv1 ----------
    {
        dim3 grid((256 + BN - 1) / BN, (n + BM - 1) / BM);
        gemm_kernel<false><<<grid, 256>>>(x, 128, x, 128, W1, nullptr, nullptr, nullptr,
                                          h1, n, 256, 128);
    }
    att_dots_kernel<2><<<warp_blocks, 256>>>(h1, att_src1, att_dst1, asrc1, adst1, n);
    edge_max_kernel<2><<<edge_blocks, 256>>>(ei, E, n, asrc1, adst1, ealpha, m1);
    edge_exp_kernel<2><<<edge_blocks, 256>>>(ei, E, n, ealpha, m1, s1);
    scatter_kernel<2><<<scat_blocks, 256>>>(ei, E, n, h1, ealpha, s1, x1);
    bias_add_kernel<<<(n * 256 + 255) / 256, 256>>>(x1, bias1, n * 256, 255);

    // ---------- conv2 ----------
    {
        dim3 grid((128 + BN - 1) / BN, (n + BM - 1) / BM);
        gemm_kernel<false><<<grid, 256>>>(x1, 256, x1, 256, W2, nullptr, nullptr, nullptr,
                                          h2, n, 128, 256);
    }
    att_dots_kernel<1><<<warp_blocks, 256>>>(h2, att_src2, att_dst2, asrc2, adst2, n);
    edge_max_kernel<1><<<edge_blocks, 256>>>(ei, E, n, asrc2, adst2, ealpha, m2);
    edge_exp_kernel<1><<<edge_blocks, 256>>>(ei, E, n, ealpha, m2, s2);
    scatter_kernel<1><<<scat_blocks, 256>>>(ei, E, n, h2, ealpha, s2, x2);
    bias_add_kernel<<<(n * 128 + 255) / 256, 256>>>(x2, bias2, n * 128, 127);

    // ---------- MLP head ----------
    // lin1: y_l = relu([x1|x2] @ Wl + bl)
    {
        dim3 grid((96 + BN - 1) / BN, (n + BM - 1) / BM);
        gemm_kernel<true><<<grid, 256>>>(x1, 256, x2, 128, Wl, bl, nullptr, nullptr,
                                         yl, n, 96, 384);
    }
    stats_cols_kernel<<<512, 96>>>(yl, n, 96, statL);
    bn_finalize_kernel<<<1, 96>>>(statL, gl, betal, scaleL, shiftL, n, 96);

    // mlp layer a: y_a = relu(BN(y_l) @ Wa + ba)
    {
        dim3 grid((96 + BN - 1) / BN, (n + BM - 1) / BM);
        gemm_kernel<true><<<grid, 256>>>(yl, 96, yl, 96, Wa, ba, scaleL, shiftL,
                                         ya, n, 96, 96);
    }
    stats_cols_kernel<<<512, 96>>>(ya, n, 96, statA);
    bn_finalize_kernel<<<1, 96>>>(statA, ga, betaa, scaleA, shiftA, n, 96);

    // mlp layer b: y_b = relu(BN(y_a) @ Wb + bb)
    {
        dim3 grid((2 + BN - 1) / BN, (n + BM - 1) / BM);
        gemm_kernel<true><<<grid, 256>>>(ya, 96, ya, 96, Wb, bb, scaleA, shiftA,
                                         yb, n, 2, 96);
    }
    stats2_kernel<<<256, 256>>>(yb, n, statB);
    bn_finalize_kernel<<<1, 2>>>(statB, gb, betab, scaleB, shiftB, n, 2);

    // output = BN(y_b)
    final_kernel<<<(n * 2 + 255) / 256, 256>>>(yb, scaleB, shiftB, out, n * 2);
}